// round 14
// baseline (speedup 1.0000x reference)
#include <cuda_runtime.h>
#include <cuda_bf16.h>
#include <mma.h>
#include <cstdint>

using namespace nvcuda;

#define B_SZ 256
#define IN_DIM 1024
#define NK 100
#define DK 50
#define NOUT 5000
#define NPAD 5120              // padded w cols
#define OUT_DIM 1124

#define QROW 64                // bytes per (k,i): 50 data + 14 pad (0x80)
#define QW4 4                  // uint4 words per row

// -------------------- device scratch (no cudaMalloc allowed) ---------------
__device__ __align__(16) __nv_bfloat16 g_xb[B_SZ * IN_DIM];
__device__ __align__(16) __nv_bfloat16 g_wb[IN_DIM * NPAD];
__device__ __align__(16) unsigned char g_actq8[NK * B_SZ * QROW];

// ---------------------------------------------------------------------------
// prep (fused): w -> bf16 padded ; x -> bf16 ; out init ; actq pads = 0x80
// ---------------------------------------------------------------------------
#define WCV_UNITS (IN_DIM * (NPAD / 8))  // 655360
#define XB_UNITS (B_SZ * IN_DIM / 4)     // 65536
#define OI_UNITS (B_SZ * OUT_DIM / 4)    // 71936
#define PAD_UNITS (NK * B_SZ)            // 25600
#define PREP_UNITS (WCV_UNITS + XB_UNITS + OI_UNITS + PAD_UNITS)

__global__ void prep_kernel(const float* __restrict__ x,
                            const float* __restrict__ w,
                            float* __restrict__ out) {
    int t = blockIdx.x * blockDim.x + threadIdx.x;
    if (t < WCV_UNITS) {
        int k  = t / (NPAD / 8);
        int n8 = (t % (NPAD / 8)) * 8;
        __nv_bfloat162 r[4];
        if (n8 < NOUT) {
            float4 v0 = *(const float4*)&w[(long long)k * NOUT + n8];
            float4 v1 = *(const float4*)&w[(long long)k * NOUT + n8 + 4];
            r[0] = __float22bfloat162_rn(make_float2(v0.x, v0.y));
            r[1] = __float22bfloat162_rn(make_float2(v0.z, v0.w));
            r[2] = __float22bfloat162_rn(make_float2(v1.x, v1.y));
            r[3] = __float22bfloat162_rn(make_float2(v1.z, v1.w));
        } else {
            r[0] = r[1] = r[2] = r[3] = __float22bfloat162_rn(make_float2(0.f, 0.f));
        }
        __nv_bfloat162* dst = (__nv_bfloat162*)&g_wb[(long long)k * NPAD + n8];
        dst[0] = r[0]; dst[1] = r[1]; dst[2] = r[2]; dst[3] = r[3];
        return;
    }
    t -= WCV_UNITS;
    if (t < XB_UNITS) {
        float4 v = ((const float4*)x)[t];
        __nv_bfloat162* dst = (__nv_bfloat162*)&g_xb[t * 4];
        dst[0] = __float22bfloat162_rn(make_float2(v.x, v.y));
        dst[1] = __float22bfloat162_rn(make_float2(v.z, v.w));
        return;
    }
    t -= XB_UNITS;
    if (t < OI_UNITS) {
        int row = t / (OUT_DIM / 4);
        int c4  = t % (OUT_DIM / 4);
        float4 v = make_float4(0.f, 0.f, 0.f, 0.f);
        if (c4 < IN_DIM / 4) v = ((const float4*)x)[row * (IN_DIM / 4) + c4];
        ((float4*)out)[row * (OUT_DIM / 4) + c4] = v;
        return;
    }
    t -= OI_UNITS;
    if (t < PAD_UNITS) {
        unsigned char* p = &g_actq8[t * QROW];
        *(unsigned short*)(p + 50) = 0x8080;
        *(unsigned*)(p + 52) = 0x80808080u;
        *(unsigned*)(p + 56) = 0x80808080u;
        *(unsigned*)(p + 60) = 0x80808080u;
    }
}

__global__ void nop_kernel() {}

// ---------------------------------------------------------------------------
// GEMM: 128x64 CTA tile, 4 warps (2x2), warp tile 64x32 (8 wmma accums).
// grid (80,2)=160 CTAs -> ALL 148 SMs busy (R13 per-SM shape, full chip).
// cp.async 3-stage pipeline; fused u8 quantization epilogue.
// ---------------------------------------------------------------------------
#define GBM 128
#define GBN 64
#define GBK 64
#define ALD 72
#define BLD 72
#define A_ST (GBM * ALD)              // 9216 elems
#define B_ST (GBK * BLD)              // 4608 elems
#define STAGE_E (A_ST + B_ST)         // 13824 elems
#define STAGES 3
#define GSMEM (STAGES * STAGE_E * 2)  // 82944 B
#define NIT (IN_DIM / GBK)            // 16
#define QCV 32.0f

__device__ __forceinline__ void cpa16(uint32_t saddr, const void* g) {
    asm volatile("cp.async.cg.shared.global [%0], [%1], 16;"
                 :: "r"(saddr), "l"(g) : "memory");
}
__device__ __forceinline__ void cpa_commit() {
    asm volatile("cp.async.commit_group;" ::: "memory");
}
template <int N>
__device__ __forceinline__ void cpa_wait() {
    asm volatile("cp.async.wait_group %0;" :: "n"(N) : "memory");
}

__global__ __launch_bounds__(128) void gemm_kernel() {
    extern __shared__ __align__(16) unsigned char smem[];
    __nv_bfloat16* Sb = (__nv_bfloat16*)smem;
    uint32_t sbase = (uint32_t)__cvta_generic_to_shared(smem);

    int tid = threadIdx.x;
    int warp = tid >> 5;
    int n0 = blockIdx.x * GBN;
    int m0 = blockIdx.y * GBM;
    int wm = (warp >> 1) * 64;       // 0, 64
    int wn = (warp & 1) * 32;        // 0, 32

    auto issue = [&](int kt) {
        int st = kt % STAGES;
        uint32_t ab = sbase + st * STAGE_E * 2;
        uint32_t bb = ab + A_ST * 2;
        int kk = kt * GBK;
        #pragma unroll
        for (int p = 0; p < 8; p++) {            // A: 128x64 = 1024 chunks
            int idx = tid + p * 128;
            int r = idx >> 3, c8 = (idx & 7) * 8;
            cpa16(ab + (r * ALD + c8) * 2, &g_xb[(m0 + r) * IN_DIM + kk + c8]);
        }
        #pragma unroll
        for (int p = 0; p < 4; p++) {            // B: 64x64 = 512 chunks
            int idx = tid + p * 128;
            int r = idx >> 3, c8 = (idx & 7) * 8;
            cpa16(bb + (r * BLD + c8) * 2, &g_wb[(long long)(kk + r) * NPAD + n0 + c8]);
        }
    };

    wmma::fragment<wmma::matrix_a, 16, 16, 16, __nv_bfloat16, wmma::row_major> af[4];
    wmma::fragment<wmma::matrix_b, 16, 16, 16, __nv_bfloat16, wmma::row_major> bf[2];
    wmma::fragment<wmma::accumulator, 16, 16, 16, float> acc[4][2];
    #pragma unroll
    for (int i = 0; i < 4; i++)
        #pragma unroll
        for (int j = 0; j < 2; j++) wmma::fill_fragment(acc[i][j], 0.0f);

    issue(0); cpa_commit();
    issue(1); cpa_commit();

    for (int kt = 0; kt < NIT; kt++) {
        cpa_wait<1>();
        __syncthreads();
        if (kt + 2 < NIT) issue(kt + 2);
        cpa_commit();

        const __nv_bfloat16* Ab = Sb + (kt % STAGES) * STAGE_E;
        const __nv_bfloat16* Bb = Ab + A_ST;
        #pragma unroll
        for (int ks = 0; ks < GBK / 16; ks++) {
            #pragma unroll
            for (int i = 0; i < 4; i++)
                wmma::load_matrix_sync(af[i], Ab + (wm + i * 16) * ALD + ks * 16, ALD);
            #pragma unroll
            for (int j = 0; j < 2; j++)
                wmma::load_matrix_sync(bf[j], Bb + (ks * 16) * BLD + wn + j * 16, BLD);
            #pragma unroll
            for (int i = 0; i < 4; i++)
                #pragma unroll
                for (int j = 0; j < 2; j++)
                    wmma::mma_sync(acc[i][j], af[i], bf[j], acc[i][j]);
        }
    }

    // ---- fused quantization epilogue ----
    __syncthreads();
    float* Es = (float*)smem;                // [128][68]
    #pragma unroll
    for (int i = 0; i < 4; i++)
        #pragma unroll
        for (int j = 0; j < 2; j++)
            wmma::store_matrix_sync(&Es[(wm + i * 16) * 68 + wn + j * 16],
                                    acc[i][j], 68, wmma::mem_row_major);
    __syncthreads();

    #pragma unroll 4
    for (int p = 0; p < (GBM * GBN) / 128; p++) {    // 64 elems/thread
        int idx = tid + p * 128;
        int row = idx >> 6;
        int col = idx & 63;
        int n = n0 + col;
        if (n < NOUT) {
            float v = Es[row * 68 + col];
            int qi = __float2int_rn(v * QCV);
            qi = max(-127, min(127, qi)) + 128;
            int k = n / DK;
            int d = n - k * DK;
            g_actq8[(k * B_SZ + m0 + row) * QROW + d] = (unsigned char)qi;
        }
    }
}

// ---------------------------------------------------------------------------
// features via u8 SIMD SAD, 16-word rows -> LDS.128 path.
// grid (NK, 8), 32-row j-chunks, 256 threads = 256 i.
// ---------------------------------------------------------------------------
#define JC 32

__device__ __forceinline__ unsigned vad4(unsigned a, unsigned b, unsigned c) {
    unsigned d;
    asm("vabsdiff4.u32.u32.u32.add %0, %1, %2, %3;"
        : "=r"(d) : "r"(a), "r"(b), "r"(c));
    return d;
}

__global__ __launch_bounds__(256) void feature_kernel(float* __restrict__ out) {
    __shared__ uint4 Aj[JC][QW4];
    int k   = blockIdx.x;
    int j0  = blockIdx.y * JC;
    int tid = threadIdx.x;
    const uint4* actk = (const uint4*)&g_actq8[(long long)k * B_SZ * QROW];

    // stage j-chunk: 32 rows x 4 uint4 = 128 vec loads
    if (tid < JC * QW4)
        Aj[tid >> 2][tid & 3] = actk[(j0 + (tid >> 2)) * QW4 + (tid & 3)];

    uint4 ai[QW4];
    #pragma unroll
    for (int c = 0; c < QW4; c++) ai[c] = actk[tid * QW4 + c];
    __syncthreads();

    float s = 0.0f;
    #pragma unroll 2
    for (int j = 0; j < JC; j++) {
        unsigned l0 = 0, l1 = 0, l2 = 0, l3 = 0;
        #pragma unroll
        for (int c = 0; c < QW4; c++) {
            uint4 b = Aj[j][c];
            l0 = vad4(ai[c].x, b.x, l0);
            l1 = vad4(ai[c].y, b.y, l1);
            l2 = vad4(ai[c].z, b.z, l2);
            l3 = vad4(ai[c].w, b.w, l3);
        }
        unsigned tot = (l0 + l1) + (l2 + l3);
        s += __expf((float)tot * (-1.0f / 32.0f));
    }
    atomicAdd(&out[tid * OUT_DIM + IN_DIM + k], s);
}

// ---------------------------------------------------------------------------
extern "C" void kernel_launch(void* const* d_in, const int* in_sizes, int n_in,
                              void* d_out, int out_size) {
    const float* x = (const float*)d_in[0];
    const float* w = (const float*)d_in[1];
    float* out = (float*)d_out;

    cudaFuncSetAttribute(gemm_kernel,
                         cudaFuncAttributeMaxDynamicSharedMemorySize, GSMEM);

    // 6 launches; GEMM stays at position 3 for the fixed ncu capture index.
    prep_kernel<<<(PREP_UNITS + 255) / 256, 256>>>(x, w, out);          // 0
    nop_kernel<<<1, 32>>>();                                            // 1
    nop_kernel<<<1, 32>>>();                                            // 2

    dim3 ggrid(NPAD / GBN, B_SZ / GBM);     // (80, 2) = 160 CTAs
    gemm_kernel<<<ggrid, 128, GSMEM>>>();                               // 3

    dim3 fgrid(NK, B_SZ / JC);              // (100, 8)
    feature_kernel<<<fgrid, 256>>>(out);                                // 4
    nop_kernel<<<1, 32>>>();                                            // 5
}

// round 15
// speedup vs baseline: 1.0868x; 1.0868x over previous
#include <cuda_runtime.h>
#include <cuda_bf16.h>
#include <mma.h>
#include <cstdint>

using namespace nvcuda;

#define B_SZ 256
#define IN_DIM 1024
#define NK 100
#define DK 50
#define NOUT 5000
#define NPAD 5920              // 74 tiles of 80 -> 148-CTA single wave
#define OUT_DIM 1124

#define QROW 64                // bytes per (k,i): 50 data + 14 pad (0x80)
#define QW4 4                  // uint4 per row

// -------------------- device scratch (no cudaMalloc allowed) ---------------
__device__ __align__(16) __nv_bfloat16 g_xb[B_SZ * IN_DIM];
__device__ __align__(16) __nv_bfloat16 g_wb[IN_DIM * NPAD];
__device__ __align__(16) unsigned char g_actq8[NK * B_SZ * QROW];

// ---------------------------------------------------------------------------
// prep (fused): w -> bf16 padded ; x -> bf16 ; out init ; actq pads = 0x80
// ---------------------------------------------------------------------------
#define WCV_UNITS (IN_DIM * (NPAD / 8))  // 757760
#define XB_UNITS (B_SZ * IN_DIM / 4)     // 65536
#define OI_UNITS (B_SZ * OUT_DIM / 4)    // 71936
#define PAD_UNITS (NK * B_SZ)            // 25600
#define PREP_UNITS (WCV_UNITS + XB_UNITS + OI_UNITS + PAD_UNITS)

__global__ void prep_kernel(const float* __restrict__ x,
                            const float* __restrict__ w,
                            float* __restrict__ out) {
    int t = blockIdx.x * blockDim.x + threadIdx.x;
    if (t < WCV_UNITS) {
        int k  = t / (NPAD / 8);
        int n8 = (t % (NPAD / 8)) * 8;
        __nv_bfloat162 r[4];
        if (n8 < NOUT) {
            float4 v0 = *(const float4*)&w[(long long)k * NOUT + n8];
            float4 v1 = *(const float4*)&w[(long long)k * NOUT + n8 + 4];
            r[0] = __float22bfloat162_rn(make_float2(v0.x, v0.y));
            r[1] = __float22bfloat162_rn(make_float2(v0.z, v0.w));
            r[2] = __float22bfloat162_rn(make_float2(v1.x, v1.y));
            r[3] = __float22bfloat162_rn(make_float2(v1.z, v1.w));
        } else {
            r[0] = r[1] = r[2] = r[3] = __float22bfloat162_rn(make_float2(0.f, 0.f));
        }
        __nv_bfloat162* dst = (__nv_bfloat162*)&g_wb[(long long)k * NPAD + n8];
        dst[0] = r[0]; dst[1] = r[1]; dst[2] = r[2]; dst[3] = r[3];
        return;
    }
    t -= WCV_UNITS;
    if (t < XB_UNITS) {
        float4 v = ((const float4*)x)[t];
        __nv_bfloat162* dst = (__nv_bfloat162*)&g_xb[t * 4];
        dst[0] = __float22bfloat162_rn(make_float2(v.x, v.y));
        dst[1] = __float22bfloat162_rn(make_float2(v.z, v.w));
        return;
    }
    t -= XB_UNITS;
    if (t < OI_UNITS) {
        int row = t / (OUT_DIM / 4);
        int c4  = t % (OUT_DIM / 4);
        float4 v = make_float4(0.f, 0.f, 0.f, 0.f);
        if (c4 < IN_DIM / 4) v = ((const float4*)x)[row * (IN_DIM / 4) + c4];
        ((float4*)out)[row * (OUT_DIM / 4) + c4] = v;
        return;
    }
    t -= OI_UNITS;
    if (t < PAD_UNITS) {
        unsigned char* p = &g_actq8[t * QROW];
        *(unsigned short*)(p + 50) = 0x8080;
        *(unsigned*)(p + 52) = 0x80808080u;
        *(unsigned*)(p + 56) = 0x80808080u;
        *(unsigned*)(p + 60) = 0x80808080u;
    }
}

__global__ void nop_kernel() {}

// ---------------------------------------------------------------------------
// GEMM: 128x80 CTA tile, grid (74,2)=148 CTAs = ONE wave on the full chip.
// 4 warps as 4Mx1N: warp tile 32x80 (2x5 m16n16k16 accums, ILP=10).
// cp.async 3-stage pipeline; fused u8 quantization epilogue.
// ---------------------------------------------------------------------------
#define GBM 128
#define GBN 80
#define GBK 64
#define ALD 72                        // A row stride elems (144 B)
#define BLD 88                        // B row stride elems (176 B)
#define A_ST (GBM * ALD)              // 9216 elems
#define B_ST (GBK * BLD)              // 5632 elems
#define STAGE_E (A_ST + B_ST)         // 14848 elems
#define STAGES 3
#define GSMEM (STAGES * STAGE_E * 2)  // 89088 B
#define NIT (IN_DIM / GBK)            // 16
#define ELD 84                        // epilogue fp32 row stride
#define QCV 32.0f

__device__ __forceinline__ void cpa16(uint32_t saddr, const void* g) {
    asm volatile("cp.async.cg.shared.global [%0], [%1], 16;"
                 :: "r"(saddr), "l"(g) : "memory");
}
__device__ __forceinline__ void cpa_commit() {
    asm volatile("cp.async.commit_group;" ::: "memory");
}
template <int N>
__device__ __forceinline__ void cpa_wait() {
    asm volatile("cp.async.wait_group %0;" :: "n"(N) : "memory");
}

__global__ __launch_bounds__(128) void gemm_kernel() {
    extern __shared__ __align__(16) unsigned char smem[];
    __nv_bfloat16* Sb = (__nv_bfloat16*)smem;
    uint32_t sbase = (uint32_t)__cvta_generic_to_shared(smem);

    int tid = threadIdx.x;
    int warp = tid >> 5;
    int n0 = blockIdx.x * GBN;
    int m0 = blockIdx.y * GBM;
    int wm = warp * 32;              // 4 warps stacked along M

    auto issue = [&](int kt) {
        int st = kt % STAGES;
        uint32_t ab = sbase + st * STAGE_E * 2;
        uint32_t bb = ab + A_ST * 2;
        int kk = kt * GBK;
        #pragma unroll
        for (int p = 0; p < 8; p++) {            // A: 128x64 = 1024 chunks
            int idx = tid + p * 128;
            int r = idx >> 3, c8 = (idx & 7) * 8;
            cpa16(ab + (r * ALD + c8) * 2, &g_xb[(m0 + r) * IN_DIM + kk + c8]);
        }
        #pragma unroll
        for (int p = 0; p < 5; p++) {            // B: 64x80 = 640 chunks
            int idx = tid + p * 128;
            int r = idx / 10, c8 = (idx % 10) * 8;
            cpa16(bb + (r * BLD + c8) * 2, &g_wb[(long long)(kk + r) * NPAD + n0 + c8]);
        }
    };

    wmma::fragment<wmma::matrix_a, 16, 16, 16, __nv_bfloat16, wmma::row_major> af[2];
    wmma::fragment<wmma::matrix_b, 16, 16, 16, __nv_bfloat16, wmma::row_major> bf[5];
    wmma::fragment<wmma::accumulator, 16, 16, 16, float> acc[2][5];
    #pragma unroll
    for (int i = 0; i < 2; i++)
        #pragma unroll
        for (int j = 0; j < 5; j++) wmma::fill_fragment(acc[i][j], 0.0f);

    issue(0); cpa_commit();
    issue(1); cpa_commit();

    for (int kt = 0; kt < NIT; kt++) {
        cpa_wait<1>();
        __syncthreads();
        if (kt + 2 < NIT) issue(kt + 2);
        cpa_commit();

        const __nv_bfloat16* Ab = Sb + (kt % STAGES) * STAGE_E;
        const __nv_bfloat16* Bb = Ab + A_ST;
        #pragma unroll
        for (int ks = 0; ks < GBK / 16; ks++) {
            #pragma unroll
            for (int i = 0; i < 2; i++)
                wmma::load_matrix_sync(af[i], Ab + (wm + i * 16) * ALD + ks * 16, ALD);
            #pragma unroll
            for (int j = 0; j < 5; j++)
                wmma::load_matrix_sync(bf[j], Bb + (ks * 16) * BLD + j * 16, BLD);
            #pragma unroll
            for (int i = 0; i < 2; i++)
                #pragma unroll
                for (int j = 0; j < 5; j++)
                    wmma::mma_sync(acc[i][j], af[i], bf[j], acc[i][j]);
        }
    }

    // ---- fused quantization epilogue ----
    __syncthreads();
    float* Es = (float*)smem;                // [128][84]
    #pragma unroll
    for (int i = 0; i < 2; i++)
        #pragma unroll
        for (int j = 0; j < 5; j++)
            wmma::store_matrix_sync(&Es[(wm + i * 16) * ELD + j * 16],
                                    acc[i][j], ELD, wmma::mem_row_major);
    __syncthreads();

    #pragma unroll 4
    for (int p = 0; p < (GBM * GBN) / 128; p++) {    // 80 elems/thread
        int idx = tid + p * 128;
        int row = idx / GBN;
        int col = idx % GBN;
        int n = n0 + col;
        if (n < NOUT) {
            float v = Es[row * ELD + col];
            int qi = __float2int_rn(v * QCV);
            qi = max(-127, min(127, qi)) + 128;
            int k = n / DK;
            int d = n - k * DK;
            g_actq8[(k * B_SZ + m0 + row) * QROW + d] = (unsigned char)qi;
        }
    }
}

// ---------------------------------------------------------------------------
// features via u8 SIMD SAD, 16-word rows -> LDS.128 path.
// grid (NK, 8), 32-row j-chunks, 256 threads = 256 i.
// ---------------------------------------------------------------------------
#define JC 32

__device__ __forceinline__ unsigned vad4(unsigned a, unsigned b, unsigned c) {
    unsigned d;
    asm("vabsdiff4.u32.u32.u32.add %0, %1, %2, %3;"
        : "=r"(d) : "r"(a), "r"(b), "r"(c));
    return d;
}

__global__ __launch_bounds__(256) void feature_kernel(float* __restrict__ out) {
    __shared__ uint4 Aj[JC][QW4];
    int k   = blockIdx.x;
    int j0  = blockIdx.y * JC;
    int tid = threadIdx.x;
    const uint4* actk = (const uint4*)&g_actq8[(long long)k * B_SZ * QROW];

    if (tid < JC * QW4)
        Aj[tid >> 2][tid & 3] = actk[(j0 + (tid >> 2)) * QW4 + (tid & 3)];

    uint4 ai[QW4];
    #pragma unroll
    for (int c = 0; c < QW4; c++) ai[c] = actk[tid * QW4 + c];
    __syncthreads();

    float s = 0.0f;
    #pragma unroll 2
    for (int j = 0; j < JC; j++) {
        unsigned l0 = 0, l1 = 0, l2 = 0, l3 = 0;
        #pragma unroll
        for (int c = 0; c < QW4; c++) {
            uint4 b = Aj[j][c];
            l0 = vad4(ai[c].x, b.x, l0);
            l1 = vad4(ai[c].y, b.y, l1);
            l2 = vad4(ai[c].z, b.z, l2);
            l3 = vad4(ai[c].w, b.w, l3);
        }
        unsigned tot = (l0 + l1) + (l2 + l3);
        s += __expf((float)tot * (-1.0f / 32.0f));
    }
    atomicAdd(&out[tid * OUT_DIM + IN_DIM + k], s);
}

// ---------------------------------------------------------------------------
extern "C" void kernel_launch(void* const* d_in, const int* in_sizes, int n_in,
                              void* d_out, int out_size) {
    const float* x = (const float*)d_in[0];
    const float* w = (const float*)d_in[1];
    float* out = (float*)d_out;

    cudaFuncSetAttribute(gemm_kernel,
                         cudaFuncAttributeMaxDynamicSharedMemorySize, GSMEM);

    // 6 launches; GEMM stays at position 3 for the fixed ncu capture index.
    prep_kernel<<<(PREP_UNITS + 255) / 256, 256>>>(x, w, out);          // 0
    nop_kernel<<<1, 32>>>();                                            // 1
    nop_kernel<<<1, 32>>>();                                            // 2

    dim3 ggrid(NPAD / GBN, B_SZ / GBM);     // (74, 2) = 148 CTAs, one wave
    gemm_kernel<<<ggrid, 128, GSMEM>>>();                               // 3

    dim3 fgrid(NK, B_SZ / JC);              // (100, 8)
    feature_kernel<<<fgrid, 256>>>(out);                                // 4
    nop_kernel<<<1, 32>>>();                                            // 5
}